// round 1
// baseline (speedup 1.0000x reference)
#include <cuda_runtime.h>
#include <cstdint>
#include <math.h>

#define NB 128   // batch
#define NT 512   // time
#define NF 256   // features
#define NH 512   // hidden
#define NG 2048  // 4*H
#define NBLK 128 // recurrence grid

// Scratch (device globals: allocation-free rule)
__device__ float g_xz[(size_t)NB * NT * NG];   // [B*T, 4H] input projections
__device__ float g_hT[2][NH * NB];             // h transposed [H][B], double buffered
__device__ unsigned g_bar;                     // grid barrier counter

__device__ __forceinline__ void cp16(void* smem_dst, const void* gmem_src) {
    unsigned s = (unsigned)__cvta_generic_to_shared(smem_dst);
    asm volatile("cp.async.cg.shared.global [%0], [%1], 16;" :: "r"(s), "l"(gmem_src));
}
__device__ __forceinline__ void cp_commit() { asm volatile("cp.async.commit_group;"); }
__device__ __forceinline__ void cp_wait0()  { asm volatile("cp.async.wait_group 0;"); }

__global__ void reset_bar_kernel() { g_bar = 0u; }

// ---------------------------------------------------------------------------
// Kernel A: xz = x @ W + bias     (M=65536, K=256, N=2048) fp32
// Block tile 128x64, K-chunk 16, 256 threads, thread tile 8x4.
// ---------------------------------------------------------------------------
__device__ __forceinline__ void gemm_stage(float* As, float* Bs,
                                           const float* __restrict__ x,
                                           const float* __restrict__ w,
                                           int m0, int n0, int tid, int buf, int kc) {
    const int k0 = kc * 16;
    // A tile: 128 rows x 16 k = 512 float4s
#pragma unroll
    for (int j = 0; j < 2; j++) {
        int f4 = tid + j * 256;
        int am = f4 >> 2, aq = f4 & 3;
        cp16(&As[buf * (128 * 20) + am * 20 + aq * 4],
             x + (size_t)(m0 + am) * NF + (k0 + aq * 4));
    }
    // B tile: 16 rows x 64 n = 256 float4s
    {
        int bk = tid >> 4, bq = tid & 15;
        cp16(&Bs[buf * (16 * 72) + bk * 72 + bq * 4],
             w + (size_t)(k0 + bk) * NG + (n0 + bq * 4));
    }
    cp_commit();
}

__global__ __launch_bounds__(256) void xz_gemm_kernel(const float* __restrict__ x,
                                                      const float* __restrict__ w,
                                                      const float* __restrict__ bias) {
    __shared__ float As[2 * 128 * 20];  // [buf][m][k(16)+pad4]
    __shared__ float Bs[2 * 16 * 72];   // [buf][k][n(64)+pad8]
    const int tid = threadIdx.x;
    const int m0 = blockIdx.y * 128;
    const int n0 = blockIdx.x * 64;
    const int tm = tid >> 4, tn = tid & 15;

    float acc[8][4];
#pragma unroll
    for (int r = 0; r < 8; r++)
#pragma unroll
        for (int c = 0; c < 4; c++) acc[r][c] = 0.f;

    gemm_stage(As, Bs, x, w, m0, n0, tid, 0, 0);

    for (int kc = 0; kc < 16; kc++) {
        cp_wait0();
        __syncthreads();
        if (kc + 1 < 16) gemm_stage(As, Bs, x, w, m0, n0, tid, (kc + 1) & 1, kc + 1);
        const int buf = kc & 1;
        const float* Ab = As + buf * (128 * 20);
        const float* Bb = Bs + buf * (16 * 72);
#pragma unroll
        for (int kk = 0; kk < 16; kk++) {
            float4 bv = *(const float4*)&Bb[kk * 72 + tn * 4];
            float a[8];
#pragma unroll
            for (int r = 0; r < 8; r++) a[r] = Ab[(tm * 8 + r) * 20 + kk];
#pragma unroll
            for (int r = 0; r < 8; r++) {
                acc[r][0] = fmaf(a[r], bv.x, acc[r][0]);
                acc[r][1] = fmaf(a[r], bv.y, acc[r][1]);
                acc[r][2] = fmaf(a[r], bv.z, acc[r][2]);
                acc[r][3] = fmaf(a[r], bv.w, acc[r][3]);
            }
        }
    }

    float4 bv = *(const float4*)(bias + n0 + tn * 4);
#pragma unroll
    for (int r = 0; r < 8; r++) {
        float4 o;
        o.x = acc[r][0] + bv.x;
        o.y = acc[r][1] + bv.y;
        o.z = acc[r][2] + bv.z;
        o.w = acc[r][3] + bv.w;
        *(float4*)&g_xz[(size_t)(m0 + tm * 8 + r) * NG + n0 + tn * 4] = o;
    }
}

// ---------------------------------------------------------------------------
// Kernel B: persistent LSTM recurrence. 128 blocks x 256 threads.
// Block owns 4 hidden columns (16 gate cols). R slice resident in smem.
// Per step: z = xz_t + h @ R_slice; gates; c,h update; 1 grid barrier.
// Thread tile: 4 batches x 4 gate cols, k split in 2 halves (256 each).
// h global layout is transposed [H][B] so smem staging [k][b] is direct.
// ---------------------------------------------------------------------------
#define HSROW 132  // 128 + 4 pad

__device__ __forceinline__ void rec_stage(float* hs, const float* __restrict__ hsrc,
                                          int tid, int buf, int j) {
#pragma unroll
    for (int i = 0; i < 8; i++) {
        int f4 = tid + i * 256;
        int r = f4 >> 5, bq = f4 & 31;                 // row in [0,64), b-quad
        int kg = (r >> 5) * 256 + 32 * j + (r & 31);   // global k
        cp16(&hs[buf * (64 * HSROW) + r * HSROW + bq * 4],
             hsrc + (size_t)kg * NB + bq * 4);
    }
    cp_commit();
}

__global__ __launch_bounds__(256) void lstm_rec_kernel(const float* __restrict__ rker,
                                                       float* __restrict__ out) {
    extern __shared__ float sm[];
    float* Rs = sm;                       // [512][16]           32 KB
    float* hs = Rs + 512 * 16;            // [2][64][132]        67.6 KB
    float* ps = hs + 2 * 64 * HSROW;      // [2][16][128]        16 KB
    float* cs = ps + 2 * 16 * 128;        // [4][128]            2 KB

    const int tid = threadIdx.x;
    const int blk = blockIdx.x;

    // Load R slice: Rs[k][c], c = gate*4 + j  -> global col gate*512 + blk*4 + j
    for (int i = tid; i < 512 * 16; i += 256) {
        int k = i >> 4, c = i & 15;
        Rs[i] = rker[(size_t)k * NG + (size_t)(c >> 2) * NH + blk * 4 + (c & 3)];
    }
    for (int i = tid; i < 512; i += 256) cs[i] = 0.f;
    __syncthreads();

    const int ks = tid >> 7;          // k half 0/1
    const int cg = (tid >> 5) & 3;    // gate index (4 cols of that gate)
    const int bg = tid & 31;          // batch group (4 batches)
    const int b0 = bg * 4, c0 = cg * 4;

    for (int t = 0; t < NT; t++) {
        float acc[4][4];
        if (t > 0) {
#pragma unroll
            for (int i = 0; i < 4; i++)
#pragma unroll
                for (int j2 = 0; j2 < 4; j2++) acc[i][j2] = 0.f;

            const float* hsrc = g_hT[t & 1];
            rec_stage(hs, hsrc, tid, 0, 0);

            for (int j = 0; j < 8; j++) {
                cp_wait0();
                __syncthreads();
                if (j + 1 < 8) rec_stage(hs, hsrc, tid, (j + 1) & 1, j + 1);

                const float* hb = hs + (j & 1) * (64 * HSROW) + (ks * 32) * HSROW;
                const float* rb2 = Rs + (ks * 256 + 32 * j) * 16;
#pragma unroll
                for (int kk = 0; kk < 32; kk++) {
                    float4 hv = *(const float4*)&hb[kk * HSROW + b0];
                    float4 rv = *(const float4*)&rb2[kk * 16 + c0];
                    acc[0][0] = fmaf(hv.x, rv.x, acc[0][0]);
                    acc[0][1] = fmaf(hv.x, rv.y, acc[0][1]);
                    acc[0][2] = fmaf(hv.x, rv.z, acc[0][2]);
                    acc[0][3] = fmaf(hv.x, rv.w, acc[0][3]);
                    acc[1][0] = fmaf(hv.y, rv.x, acc[1][0]);
                    acc[1][1] = fmaf(hv.y, rv.y, acc[1][1]);
                    acc[1][2] = fmaf(hv.y, rv.z, acc[1][2]);
                    acc[1][3] = fmaf(hv.y, rv.w, acc[1][3]);
                    acc[2][0] = fmaf(hv.z, rv.x, acc[2][0]);
                    acc[2][1] = fmaf(hv.z, rv.y, acc[2][1]);
                    acc[2][2] = fmaf(hv.z, rv.z, acc[2][2]);
                    acc[2][3] = fmaf(hv.z, rv.w, acc[2][3]);
                    acc[3][0] = fmaf(hv.w, rv.x, acc[3][0]);
                    acc[3][1] = fmaf(hv.w, rv.y, acc[3][1]);
                    acc[3][2] = fmaf(hv.w, rv.z, acc[3][2]);
                    acc[3][3] = fmaf(hv.w, rv.w, acc[3][3]);
                }
            }
            // partial sums: ps[ks][c][b]
#pragma unroll
            for (int bb = 0; bb < 4; bb++)
#pragma unroll
                for (int cc2 = 0; cc2 < 4; cc2++)
                    ps[ks * 2048 + (c0 + cc2) * 128 + (b0 + bb)] = acc[bb][cc2];
        }
        __syncthreads();

        // gates + state update: thread b = tid handles 4 hidden cols
        if (tid < 128) {
            const int b = tid;
            const float* xzp = g_xz + ((size_t)b * NT + t) * NG + blk * 4;
            float z[4][4];
#pragma unroll
            for (int g = 0; g < 4; g++) {
                float4 v = *(const float4*)(xzp + g * NH);
                z[g][0] = v.x; z[g][1] = v.y; z[g][2] = v.z; z[g][3] = v.w;
            }
            if (t > 0) {
#pragma unroll
                for (int g = 0; g < 4; g++)
#pragma unroll
                    for (int j = 0; j < 4; j++)
                        z[g][j] += ps[(g * 4 + j) * 128 + b] + ps[2048 + (g * 4 + j) * 128 + b];
            }
            float hv[4], cvv[4];
#pragma unroll
            for (int j = 0; j < 4; j++) {
                float iv = 1.f / (1.f + __expf(-z[0][j]));
                float fv = 1.f / (1.f + __expf(-z[1][j]));
                float gv = tanhf(z[2][j]);
                float ov = 1.f / (1.f + __expf(-z[3][j]));
                float cc2 = fv * cs[j * 128 + b] + iv * gv;
                cs[j * 128 + b] = cc2;
                cvv[j] = cc2;
                hv[j] = ov * tanhf(cc2);
            }
            float4 h4 = make_float4(hv[0], hv[1], hv[2], hv[3]);
            *(float4*)(out + ((size_t)b * NT + t) * NH + blk * 4) = h4;
            float* hw = g_hT[(t + 1) & 1];
#pragma unroll
            for (int j = 0; j < 4; j++) hw[(size_t)(blk * 4 + j) * NB + b] = hv[j];
            if (t == NT - 1) {
                size_t off1 = (size_t)NB * NT * NH;
                *(float4*)(out + off1 + (size_t)b * NH + blk * 4) = h4;
                float4 c4 = make_float4(cvv[0], cvv[1], cvv[2], cvv[3]);
                *(float4*)(out + off1 + (size_t)NB * NH + (size_t)b * NH + blk * 4) = c4;
            }
        }

        // grid barrier (monotonic counter; reset by reset_bar_kernel each launch)
        if (t < NT - 1) {
            __threadfence();
            __syncthreads();
            if (tid == 0) {
                atomicAdd(&g_bar, 1u);
                const unsigned target = (unsigned)NBLK * (unsigned)(t + 1);
                while (*((volatile unsigned*)&g_bar) < target) {}
                __threadfence();
            }
            __syncthreads();
        }
    }
}

// ---------------------------------------------------------------------------
extern "C" void kernel_launch(void* const* d_in, const int* in_sizes, int n_in,
                              void* d_out, int out_size) {
    const float* x    = (const float*)d_in[0];  // [B,T,F]
    const float* w    = (const float*)d_in[1];  // [F,4H]
    const float* rk   = (const float*)d_in[2];  // [H,4H]
    const float* bias = (const float*)d_in[3];  // [4H]
    float* out = (float*)d_out;                 // output | h | c

    cudaFuncSetAttribute(lstm_rec_kernel,
                         cudaFuncAttributeMaxDynamicSharedMemorySize, 118784);

    reset_bar_kernel<<<1, 1>>>();
    dim3 gg(NG / 64, (NB * NT) / 128);  // (32, 512)
    xz_gemm_kernel<<<gg, 256>>>(x, w, bias);
    lstm_rec_kernel<<<NBLK, 256, 118784>>>(rk, out);
}

// round 2
// speedup vs baseline: 1.5084x; 1.5084x over previous
#include <cuda_runtime.h>
#include <cuda_bf16.h>
#include <cstdint>
#include <math.h>

#define NB 128   // batch
#define NT 512   // time
#define NF 256   // features
#define NH 512   // hidden
#define NG 2048  // 4*H
#define NBLK 128 // recurrence grid

// Scratch (device globals: allocation-free rule)
__device__ float g_xz[(size_t)NB * NT * NG];          // [B*T, 4H]
__device__ __nv_bfloat16 g_hHi[2][NB * NH];           // h bf16 hi, [b][h], double buf
__device__ __nv_bfloat16 g_hLo[2][NB * NH];           // h bf16 lo residual
__device__ unsigned g_bar;                            // grid barrier counter

__device__ __forceinline__ void cp16(void* smem_dst, const void* gmem_src) {
    unsigned s = (unsigned)__cvta_generic_to_shared(smem_dst);
    asm volatile("cp.async.cg.shared.global [%0], [%1], 16;" :: "r"(s), "l"(gmem_src));
}
__device__ __forceinline__ void cp_commit() { asm volatile("cp.async.commit_group;"); }
__device__ __forceinline__ void cp_wait0()  { asm volatile("cp.async.wait_group 0;"); }

__device__ __forceinline__ void mma_bf16(float* c, const unsigned* a, uint2 b) {
    asm volatile(
        "mma.sync.aligned.m16n8k16.row.col.f32.bf16.bf16.f32 "
        "{%0,%1,%2,%3},{%4,%5,%6,%7},{%8,%9},{%0,%1,%2,%3};"
        : "+f"(c[0]), "+f"(c[1]), "+f"(c[2]), "+f"(c[3])
        : "r"(a[0]), "r"(a[1]), "r"(a[2]), "r"(a[3]), "r"(b.x), "r"(b.y));
}
__device__ __forceinline__ void ldmat4(unsigned* a, unsigned saddr) {
    asm volatile("ldmatrix.sync.aligned.m8n8.x4.shared.b16 {%0,%1,%2,%3}, [%4];"
                 : "=r"(a[0]), "=r"(a[1]), "=r"(a[2]), "=r"(a[3]) : "r"(saddr));
}

// ---------------------------------------------------------------------------
// Kernel A: xz = x @ W + bias   (M=65536, K=256, N=2048) fp32 FFMA
// (also resets the grid-barrier counter for the recurrence kernel)
// ---------------------------------------------------------------------------
__device__ __forceinline__ void gemm_stage(float* As, float* Bs,
                                           const float* __restrict__ x,
                                           const float* __restrict__ w,
                                           int m0, int n0, int tid, int buf, int kc) {
    const int k0 = kc * 16;
#pragma unroll
    for (int j = 0; j < 2; j++) {
        int f4 = tid + j * 256;
        int am = f4 >> 2, aq = f4 & 3;
        cp16(&As[buf * (128 * 20) + am * 20 + aq * 4],
             x + (size_t)(m0 + am) * NF + (k0 + aq * 4));
    }
    {
        int bk = tid >> 4, bq = tid & 15;
        cp16(&Bs[buf * (16 * 72) + bk * 72 + bq * 4],
             w + (size_t)(k0 + bk) * NG + (n0 + bq * 4));
    }
    cp_commit();
}

__global__ __launch_bounds__(256) void xz_gemm_kernel(const float* __restrict__ x,
                                                      const float* __restrict__ w,
                                                      const float* __restrict__ bias) {
    if (blockIdx.x == 0 && blockIdx.y == 0 && threadIdx.x == 0) g_bar = 0u;

    __shared__ float As[2 * 128 * 20];
    __shared__ float Bs[2 * 16 * 72];
    const int tid = threadIdx.x;
    const int m0 = blockIdx.y * 128;
    const int n0 = blockIdx.x * 64;
    const int tm = tid >> 4, tn = tid & 15;

    float acc[8][4];
#pragma unroll
    for (int r = 0; r < 8; r++)
#pragma unroll
        for (int c = 0; c < 4; c++) acc[r][c] = 0.f;

    gemm_stage(As, Bs, x, w, m0, n0, tid, 0, 0);

    for (int kc = 0; kc < 16; kc++) {
        cp_wait0();
        __syncthreads();
        if (kc + 1 < 16) gemm_stage(As, Bs, x, w, m0, n0, tid, (kc + 1) & 1, kc + 1);
        const int buf = kc & 1;
        const float* Ab = As + buf * (128 * 20);
        const float* Bb = Bs + buf * (16 * 72);
#pragma unroll
        for (int kk = 0; kk < 16; kk++) {
            float4 bv = *(const float4*)&Bb[kk * 72 + tn * 4];
            float a[8];
#pragma unroll
            for (int r = 0; r < 8; r++) a[r] = Ab[(tm * 8 + r) * 20 + kk];
#pragma unroll
            for (int r = 0; r < 8; r++) {
                acc[r][0] = fmaf(a[r], bv.x, acc[r][0]);
                acc[r][1] = fmaf(a[r], bv.y, acc[r][1]);
                acc[r][2] = fmaf(a[r], bv.z, acc[r][2]);
                acc[r][3] = fmaf(a[r], bv.w, acc[r][3]);
            }
        }
    }

    float4 bv = *(const float4*)(bias + n0 + tn * 4);
#pragma unroll
    for (int r = 0; r < 8; r++) {
        float4 o;
        o.x = acc[r][0] + bv.x;
        o.y = acc[r][1] + bv.y;
        o.z = acc[r][2] + bv.z;
        o.w = acc[r][3] + bv.w;
        *(float4*)&g_xz[(size_t)(m0 + tm * 8 + r) * NG + n0 + tn * 4] = o;
    }
}

// ---------------------------------------------------------------------------
// Kernel B: persistent LSTM recurrence via warp mma.sync bf16 3-term split.
// 128 blocks x 256 threads. Block owns 16 gate cols (4 hidden cols x 4 gates).
// Per step: Z[128x16] = Hprev[128x512] @ Rslice[512x16] via tensor cores.
// H staged in 64-k chunks through swizzled smem; R pre-split hi/lo into
// fragment-ordered smem (1 LDS.64 per B fragment). fp32 accumulate in regs.
// ---------------------------------------------------------------------------

// smem layout (elems): Rsf[16384 bf16] | Hs[32768 bf16] | ps[2112 f32] | cs[512 f32]
// Hs: [2 buf][2 term][128 b][64 k], 128B rows with XOR-16B swizzle.

__device__ __forceinline__ void rec_stage(__nv_bfloat16* Hs,
                                          const __nv_bfloat16* __restrict__ hHi,
                                          const __nv_bfloat16* __restrict__ hLo,
                                          int tid, int buf, int ch) {
    const int k0 = ch * 64;
    char* base = (char*)(Hs + buf * 16384);
#pragma unroll
    for (int i2 = 0; i2 < 8; i2++) {
        int f = tid + i2 * 256;          // 0..2047
        int term = f >> 10;              // 0 = hi, 1 = lo
        int rem = f & 1023;
        int b = rem >> 3, s = rem & 7;
        const __nv_bfloat16* src = (term ? hLo : hHi) + (size_t)b * NH + k0 + s * 8;
        unsigned byteoff = (unsigned)(b * 128 + ((s * 16) ^ ((b & 7) << 4)));
        cp16(base + term * 16384 + byteoff, src);
    }
    cp_commit();
}

__global__ __launch_bounds__(256) void lstm_rec_kernel(const float* __restrict__ rker,
                                                       float* __restrict__ out) {
    extern __shared__ char smraw[];
    __nv_bfloat16* Rsf = (__nv_bfloat16*)smraw;     // 16384 elems (32KB)
    __nv_bfloat16* Hs  = Rsf + 16384;               // 32768 elems (64KB)
    float* ps = (float*)(Hs + 32768);               // [16][132]
    float* cs = ps + 16 * 132;                      // [4][128]

    const int tid = threadIdx.x;
    const int blk = blockIdx.x;
    const int w = tid >> 5, lane = tid & 31;

    // ---- one-time: pre-split R slice into fragment-ordered smem ----
    // entry i = term*2048 + kk*64 + nn*32 + lane ; each entry = 4 bf16 (uint2)
    for (int i = tid; i < 4096; i += 256) {
        int l = i & 31, nn = (i >> 5) & 1, kk = (i >> 6) & 31, term = i >> 11;
        int c = l & 3, n = nn * 8 + (l >> 2);
        int gc = (n >> 2) * NH + blk * 4 + (n & 3);
        int kb = kk * 16 + c * 2;
        float e0 = rker[(size_t)(kb + 0) * NG + gc];
        float e1 = rker[(size_t)(kb + 1) * NG + gc];
        float e2 = rker[(size_t)(kb + 8) * NG + gc];
        float e3 = rker[(size_t)(kb + 9) * NG + gc];
        __nv_bfloat16 v0, v1, v2, v3;
        if (term == 0) {
            v0 = __float2bfloat16_rn(e0); v1 = __float2bfloat16_rn(e1);
            v2 = __float2bfloat16_rn(e2); v3 = __float2bfloat16_rn(e3);
        } else {
            __nv_bfloat16 h0 = __float2bfloat16_rn(e0), h1 = __float2bfloat16_rn(e1);
            __nv_bfloat16 h2 = __float2bfloat16_rn(e2), h3 = __float2bfloat16_rn(e3);
            v0 = __float2bfloat16_rn(e0 - __bfloat162float(h0));
            v1 = __float2bfloat16_rn(e1 - __bfloat162float(h1));
            v2 = __float2bfloat16_rn(e2 - __bfloat162float(h2));
            v3 = __float2bfloat16_rn(e3 - __bfloat162float(h3));
        }
        __nv_bfloat16* dst = Rsf + (size_t)i * 4;
        dst[0] = v0; dst[1] = v1; dst[2] = v2; dst[3] = v3;
    }
    for (int i = tid; i < 512; i += 256) cs[i] = 0.f;
    __syncthreads();

    const uint2* Rf2 = (const uint2*)Rsf;
    const unsigned sHs = (unsigned)__cvta_generic_to_shared(Hs);
    // ldmatrix per-thread address components
    const int brow = w * 16 + (lane & 15);
    const unsigned abase = (unsigned)(brow * 128);
    const unsigned axor  = (unsigned)((brow & 7) << 4);
    const unsigned ahalf = (unsigned)((lane >> 4) * 16);

    for (int t = 0; t < NT; t++) {
        if (t > 0) {
            float acc0[4] = {0.f, 0.f, 0.f, 0.f};
            float acc1[4] = {0.f, 0.f, 0.f, 0.f};
            const __nv_bfloat16* hHi = g_hHi[t & 1];
            const __nv_bfloat16* hLo = g_hLo[t & 1];
            rec_stage(Hs, hHi, hLo, tid, 0, 0);

            for (int ch = 0; ch < 8; ch++) {
                cp_wait0();
                __syncthreads();
                if (ch + 1 < 8) rec_stage(Hs, hHi, hLo, tid, (ch + 1) & 1, ch + 1);

                const unsigned sHbHi = sHs + (unsigned)((ch & 1) * 32768);
                const unsigned sHbLo = sHbHi + 16384u;
                const int kk0 = ch * 4;
#pragma unroll
                for (int kk = 0; kk < 4; kk++) {
                    unsigned ahi[4], alo[4];
                    unsigned boff = abase + (((unsigned)(kk * 32) + ahalf) ^ axor);
                    ldmat4(ahi, sHbHi + boff);
                    ldmat4(alo, sHbLo + boff);
                    const int kkg = kk0 + kk;
                    uint2 bhi0 = Rf2[kkg * 64 + lane];
                    uint2 blo0 = Rf2[2048 + kkg * 64 + lane];
                    uint2 bhi1 = Rf2[kkg * 64 + 32 + lane];
                    uint2 blo1 = Rf2[2048 + kkg * 64 + 32 + lane];
                    mma_bf16(acc0, ahi, bhi0);
                    mma_bf16(acc1, ahi, bhi1);
                    mma_bf16(acc0, ahi, blo0);
                    mma_bf16(acc1, ahi, blo1);
                    mma_bf16(acc0, alo, bhi0);
                    mma_bf16(acc1, alo, bhi1);
                }
            }
            // scatter Z fragments to ps[col][b]
            const int g2 = lane >> 2, c2 = lane & 3;
            const int r0 = w * 16 + g2;
            {
                int cb = c2 * 2;
                ps[(cb + 0) * 132 + r0]     = acc0[0];
                ps[(cb + 1) * 132 + r0]     = acc0[1];
                ps[(cb + 0) * 132 + r0 + 8] = acc0[2];
                ps[(cb + 1) * 132 + r0 + 8] = acc0[3];
                cb = 8 + c2 * 2;
                ps[(cb + 0) * 132 + r0]     = acc1[0];
                ps[(cb + 1) * 132 + r0]     = acc1[1];
                ps[(cb + 0) * 132 + r0 + 8] = acc1[2];
                ps[(cb + 1) * 132 + r0 + 8] = acc1[3];
            }
        }
        __syncthreads();

        // gates + state update: thread b handles this block's 4 hidden cols
        if (tid < 128) {
            const int b = tid;
            const float* xzp = g_xz + ((size_t)b * NT + t) * NG + blk * 4;
            float z[4][4];
#pragma unroll
            for (int g = 0; g < 4; g++) {
                float4 v = *(const float4*)(xzp + g * NH);
                z[g][0] = v.x; z[g][1] = v.y; z[g][2] = v.z; z[g][3] = v.w;
            }
            if (t > 0) {
#pragma unroll
                for (int g = 0; g < 4; g++)
#pragma unroll
                    for (int j = 0; j < 4; j++)
                        z[g][j] += ps[(g * 4 + j) * 132 + b];
            }
            float hv[4], cvv[4];
#pragma unroll
            for (int j = 0; j < 4; j++) {
                float iv = 1.f / (1.f + __expf(-z[0][j]));
                float fv = 1.f / (1.f + __expf(-z[1][j]));
                float gv = tanhf(z[2][j]);
                float ov = 1.f / (1.f + __expf(-z[3][j]));
                float cc2 = fv * cs[j * 128 + b] + iv * gv;
                cs[j * 128 + b] = cc2;
                cvv[j] = cc2;
                hv[j] = ov * tanhf(cc2);
            }
            float4 h4 = make_float4(hv[0], hv[1], hv[2], hv[3]);
            *(float4*)(out + ((size_t)b * NT + t) * NH + blk * 4) = h4;

            __nv_bfloat16 hiv[4], lov[4];
#pragma unroll
            for (int j = 0; j < 4; j++) {
                hiv[j] = __float2bfloat16_rn(hv[j]);
                lov[j] = __float2bfloat16_rn(hv[j] - __bfloat162float(hiv[j]));
            }
            const int par = (t + 1) & 1;
            *(uint2*)(g_hHi[par] + (size_t)b * NH + blk * 4) = *(uint2*)hiv;
            *(uint2*)(g_hLo[par] + (size_t)b * NH + blk * 4) = *(uint2*)lov;

            if (t == NT - 1) {
                size_t off1 = (size_t)NB * NT * NH;
                *(float4*)(out + off1 + (size_t)b * NH + blk * 4) = h4;
                float4 c4 = make_float4(cvv[0], cvv[1], cvv[2], cvv[3]);
                *(float4*)(out + off1 + (size_t)NB * NH + (size_t)b * NH + blk * 4) = c4;
            }
        }

        // grid barrier (monotonic counter; reset by xz_gemm_kernel each launch)
        if (t < NT - 1) {
            __threadfence();
            __syncthreads();
            if (tid == 0) {
                atomicAdd(&g_bar, 1u);
                const unsigned target = (unsigned)NBLK * (unsigned)(t + 1);
                while (*((volatile unsigned*)&g_bar) < target) {}
                __threadfence();
            }
            __syncthreads();
        }
    }
}

// ---------------------------------------------------------------------------
extern "C" void kernel_launch(void* const* d_in, const int* in_sizes, int n_in,
                              void* d_out, int out_size) {
    const float* x    = (const float*)d_in[0];  // [B,T,F]
    const float* w    = (const float*)d_in[1];  // [F,4H]
    const float* rk   = (const float*)d_in[2];  // [H,4H]
    const float* bias = (const float*)d_in[3];  // [4H]
    float* out = (float*)d_out;                 // output | h | c

    cudaFuncSetAttribute(lstm_rec_kernel,
                         cudaFuncAttributeMaxDynamicSharedMemorySize, 108800);

    dim3 gg(NG / 64, (NB * NT) / 128);  // (32, 512)
    xz_gemm_kernel<<<gg, 256>>>(x, w, bias);
    lstm_rec_kernel<<<NBLK, 256, 108800>>>(rk, out);
}

// round 3
// speedup vs baseline: 2.0635x; 1.3680x over previous
#include <cuda_runtime.h>
#include <cuda_bf16.h>
#include <cstdint>
#include <math.h>

#define NB 128   // batch
#define NT 512   // time
#define NF 256   // features
#define NH 512   // hidden
#define NG 2048  // 4*H
#define NBLK 128 // recurrence grid
#define M_TOT (NB * NT)  // 65536

// Scratch (device globals: allocation-free rule)
__device__ float g_xz[(size_t)M_TOT * NG];            // [B*T, 4H]
__device__ __nv_bfloat16 g_xHi[(size_t)M_TOT * NF];   // x bf16 hi
__device__ __nv_bfloat16 g_xLo[(size_t)M_TOT * NF];   // x bf16 lo residual
__device__ uint2 g_wf[262144];                        // W frag-order [term][nblk16][k16 16][n8 16][lane 32]
__device__ __nv_bfloat16 g_hHi[2][NB * NH];           // h bf16 hi, [b][h], double buf
__device__ __nv_bfloat16 g_hLo[2][NB * NH];           // h bf16 lo residual
__device__ unsigned g_bar;                            // grid barrier counter

__device__ __forceinline__ void cp16(void* smem_dst, const void* gmem_src) {
    unsigned s = (unsigned)__cvta_generic_to_shared(smem_dst);
    asm volatile("cp.async.cg.shared.global [%0], [%1], 16;" :: "r"(s), "l"(gmem_src));
}
__device__ __forceinline__ void cp_commit() { asm volatile("cp.async.commit_group;"); }
__device__ __forceinline__ void cp_wait0()  { asm volatile("cp.async.wait_group 0;"); }
__device__ __forceinline__ void cp_wait1()  { asm volatile("cp.async.wait_group 1;"); }

__device__ __forceinline__ void mma_bf16(float* c, const unsigned* a, uint2 b) {
    asm volatile(
        "mma.sync.aligned.m16n8k16.row.col.f32.bf16.bf16.f32 "
        "{%0,%1,%2,%3},{%4,%5,%6,%7},{%8,%9},{%0,%1,%2,%3};"
        : "+f"(c[0]), "+f"(c[1]), "+f"(c[2]), "+f"(c[3])
        : "r"(a[0]), "r"(a[1]), "r"(a[2]), "r"(a[3]), "r"(b.x), "r"(b.y));
}
__device__ __forceinline__ void ldmat4(unsigned* a, unsigned saddr) {
    asm volatile("ldmatrix.sync.aligned.m8n8.x4.shared.b16 {%0,%1,%2,%3}, [%4];"
                 : "=r"(a[0]), "=r"(a[1]), "=r"(a[2]), "=r"(a[3]) : "r"(saddr));
}
__device__ __forceinline__ __nv_bfloat16 bhi(float e) { return __float2bfloat16_rn(e); }
__device__ __forceinline__ __nv_bfloat16 blo(float e) {
    __nv_bfloat16 h = __float2bfloat16_rn(e);
    return __float2bfloat16_rn(e - __bfloat162float(h));
}

// ---------------------------------------------------------------------------
// Kernel 0: convert x -> bf16 hi/lo, W -> fragment-ordered bf16 hi/lo.
// Also resets the grid barrier counter.
// ---------------------------------------------------------------------------
__global__ __launch_bounds__(256) void conv_kernel(const float* __restrict__ x,
                                                   const float* __restrict__ w) {
    if (blockIdx.x == 0 && threadIdx.x == 0) g_bar = 0u;
    const int tid = blockIdx.x * blockDim.x + threadIdx.x;
    const int nth = gridDim.x * blockDim.x;

    const float4* x4 = (const float4*)x;
    for (size_t i = tid; i < (size_t)M_TOT * NF / 4; i += nth) {
        float4 v = x4[i];
        float e[4] = {v.x, v.y, v.z, v.w};
        __nv_bfloat16 h[4], l[4];
#pragma unroll
        for (int j = 0; j < 4; j++) { h[j] = bhi(e[j]); l[j] = blo(e[j]); }
        ((uint2*)g_xHi)[i] = *(uint2*)h;
        ((uint2*)g_xLo)[i] = *(uint2*)l;
    }

    for (int j = tid; j < 262144; j += nth) {
        int lane = j & 31, n8 = (j >> 5) & 15, k16 = (j >> 9) & 15;
        int nblk = (j >> 13) & 15, term = j >> 17;
        int n = nblk * 128 + n8 * 8 + (lane >> 2);
        int k = k16 * 16 + (lane & 3) * 2;
        float e0 = w[(size_t)k * NG + n];
        float e1 = w[(size_t)(k + 1) * NG + n];
        float e2 = w[(size_t)(k + 8) * NG + n];
        float e3 = w[(size_t)(k + 9) * NG + n];
        __nv_bfloat16 v[4];
        if (term == 0) { v[0] = bhi(e0); v[1] = bhi(e1); v[2] = bhi(e2); v[3] = bhi(e3); }
        else           { v[0] = blo(e0); v[1] = blo(e1); v[2] = blo(e2); v[3] = blo(e3); }
        g_wf[j] = *(uint2*)v;
    }
}

// ---------------------------------------------------------------------------
// Kernel A: xz = x @ W + bias  via bf16 3-term mma.sync.
// Block tile 128m x 128n, kstep 64, 256 threads (8 warps: 2m x 4n, warp 64x32).
// smem: As [2buf][2term][128m][64k swizzled 128B rows] 64KB, Bs frag-order 64KB.
// ---------------------------------------------------------------------------
__device__ __forceinline__ void xza_stage(char* As, char* Bs, int m0, int nblk,
                                          int tid, int buf, int ks) {
#pragma unroll
    for (int i = 0; i < 8; i++) {
        int f = tid + i * 256;
        int term = f >> 10, rem = f & 1023, m = rem >> 3, s = rem & 7;
        const __nv_bfloat16* src = (term ? g_xLo : g_xHi) + (size_t)(m0 + m) * NF + ks * 64 + s * 8;
        cp16(As + buf * 32768 + term * 16384 + m * 128 + ((s * 16) ^ ((m & 7) << 4)), src);
    }
    const char* wsrc = (const char*)g_wf;
#pragma unroll
    for (int i = 0; i < 8; i++) {
        int f = tid + i * 256;
        int term = f >> 10, q = f & 1023;
        cp16(Bs + buf * 32768 + term * 16384 + q * 16,
             wsrc + term * 1048576 + nblk * 65536 + ks * 16384 + q * 16);
    }
    cp_commit();
}

__global__ __launch_bounds__(256) void xza_kernel(const float* __restrict__ bias) {
    extern __shared__ char sm[];
    char* As = sm;
    char* Bs = sm + 65536;
    const int tid = threadIdx.x, w = tid >> 5, lane = tid & 31;
    const int m0 = blockIdx.y * 128, nblk = blockIdx.x, n0 = nblk * 128;
    const int wm = (w >> 2) * 64, wn = (w & 3) * 32;

    float acc[4][4][4];
#pragma unroll
    for (int mt = 0; mt < 4; mt++)
#pragma unroll
        for (int nt = 0; nt < 4; nt++)
#pragma unroll
            for (int q = 0; q < 4; q++) acc[mt][nt][q] = 0.f;

    xza_stage(As, Bs, m0, nblk, tid, 0, 0);
    const unsigned sA = (unsigned)__cvta_generic_to_shared(As);
    const uint2* Bs2 = (const uint2*)Bs;

    for (int ks = 0; ks < 4; ks++) {
        cp_wait0();
        __syncthreads();
        if (ks + 1 < 4) xza_stage(As, Bs, m0, nblk, tid, (ks + 1) & 1, ks + 1);
        const int buf = ks & 1;
        const unsigned sAb = sA + (unsigned)(buf * 32768);
#pragma unroll
        for (int k16 = 0; k16 < 4; k16++) {
            unsigned aHi[4][4], aLo[4][4];
#pragma unroll
            for (int mt = 0; mt < 4; mt++) {
                int row = wm + mt * 16 + (lane & 15);
                unsigned off = (unsigned)(row * 128 +
                    (((k16 * 32) + ((lane >> 4) * 16)) ^ ((row & 7) << 4)));
                ldmat4(aHi[mt], sAb + off);
                ldmat4(aLo[mt], sAb + 16384u + off);
            }
            uint2 bHi[4], bLo[4];
#pragma unroll
            for (int nt = 0; nt < 4; nt++) {
                int n8 = (w & 3) * 4 + nt;
                bHi[nt] = Bs2[buf * 4096 + k16 * 512 + n8 * 32 + lane];
                bLo[nt] = Bs2[buf * 4096 + 2048 + k16 * 512 + n8 * 32 + lane];
            }
#pragma unroll
            for (int mt = 0; mt < 4; mt++)
#pragma unroll
                for (int nt = 0; nt < 4; nt++) {
                    mma_bf16(acc[mt][nt], aHi[mt], bHi[nt]);
                    mma_bf16(acc[mt][nt], aHi[mt], bLo[nt]);
                    mma_bf16(acc[mt][nt], aLo[mt], bHi[nt]);
                }
        }
    }

#pragma unroll
    for (int nt = 0; nt < 4; nt++) {
        int col = n0 + wn + nt * 8 + (lane & 3) * 2;
        float b0 = __ldg(bias + col), b1 = __ldg(bias + col + 1);
#pragma unroll
        for (int mt = 0; mt < 4; mt++) {
            int row = m0 + wm + mt * 16 + (lane >> 2);
            float2 v0 = make_float2(acc[mt][nt][0] + b0, acc[mt][nt][1] + b1);
            float2 v1 = make_float2(acc[mt][nt][2] + b0, acc[mt][nt][3] + b1);
            *(float2*)&g_xz[(size_t)row * NG + col] = v0;
            *(float2*)&g_xz[(size_t)(row + 8) * NG + col] = v1;
        }
    }
}

// ---------------------------------------------------------------------------
// Kernel B: persistent LSTM recurrence (bf16 3-term mma.sync).
// 128 blocks x 256 threads; block owns 16 gate cols. 3-stage cp.async pipeline.
// ---------------------------------------------------------------------------
__device__ __forceinline__ void rec_stage(__nv_bfloat16* Hs,
                                          const __nv_bfloat16* __restrict__ hHi,
                                          const __nv_bfloat16* __restrict__ hLo,
                                          int tid, int buf, int ch) {
    const int k0 = ch * 64;
    char* base = (char*)Hs + buf * 32768;
#pragma unroll
    for (int i2 = 0; i2 < 8; i2++) {
        int f = tid + i2 * 256;          // 0..2047
        int term = f >> 10;              // 0 = hi, 1 = lo
        int rem = f & 1023;
        int b = rem >> 3, s = rem & 7;
        const __nv_bfloat16* src = (term ? hLo : hHi) + (size_t)b * NH + k0 + s * 8;
        unsigned byteoff = (unsigned)(b * 128 + ((s * 16) ^ ((b & 7) << 4)));
        cp16(base + term * 16384 + byteoff, src);
    }
    cp_commit();
}

__global__ __launch_bounds__(256) void lstm_rec_kernel(const float* __restrict__ rker,
                                                       float* __restrict__ out) {
    extern __shared__ char smraw[];
    __nv_bfloat16* Rsf = (__nv_bfloat16*)smraw;     // 16384 elems (32KB)
    __nv_bfloat16* Hs  = Rsf + 16384;               // 3 bufs x 16384 elems (96KB)
    float* ps = (float*)(Hs + 3 * 16384);           // [16][132]
    float* cs = ps + 16 * 132;                      // [4][128]

    const int tid = threadIdx.x;
    const int blk = blockIdx.x;
    const int w = tid >> 5, lane = tid & 31;

    // ---- one-time: pre-split R slice into fragment-ordered smem ----
    for (int i = tid; i < 4096; i += 256) {
        int l = i & 31, nn = (i >> 5) & 1, kk = (i >> 6) & 31, term = i >> 11;
        int c = l & 3, n = nn * 8 + (l >> 2);
        int gc = (n >> 2) * NH + blk * 4 + (n & 3);
        int kb = kk * 16 + c * 2;
        float e0 = rker[(size_t)(kb + 0) * NG + gc];
        float e1 = rker[(size_t)(kb + 1) * NG + gc];
        float e2 = rker[(size_t)(kb + 8) * NG + gc];
        float e3 = rker[(size_t)(kb + 9) * NG + gc];
        __nv_bfloat16 v[4];
        if (term == 0) { v[0] = bhi(e0); v[1] = bhi(e1); v[2] = bhi(e2); v[3] = bhi(e3); }
        else           { v[0] = blo(e0); v[1] = blo(e1); v[2] = blo(e2); v[3] = blo(e3); }
        *(uint2*)(Rsf + (size_t)i * 4) = *(uint2*)v;
    }
    for (int i = tid; i < 512; i += 256) cs[i] = 0.f;
    __syncthreads();

    const uint2* Rf2 = (const uint2*)Rsf;
    const unsigned sHs = (unsigned)__cvta_generic_to_shared(Hs);
    const int brow = w * 16 + (lane & 15);
    const unsigned abase = (unsigned)(brow * 128);
    const unsigned axor  = (unsigned)((brow & 7) << 4);
    const unsigned ahalf = (unsigned)((lane >> 4) * 16);

    for (int t = 0; t < NT; t++) {
        // prefetch this step's xz slice into registers (hidden under MMA phase)
        float4 xzv[4];
        if (tid < 128) {
            const float* xzp = g_xz + ((size_t)tid * NT + t) * NG + blk * 4;
#pragma unroll
            for (int g = 0; g < 4; g++) xzv[g] = *(const float4*)(xzp + g * NH);
        }

        if (t > 0) {
            float acc0[4] = {0.f, 0.f, 0.f, 0.f};
            float acc1[4] = {0.f, 0.f, 0.f, 0.f};
            const __nv_bfloat16* hHi = g_hHi[t & 1];
            const __nv_bfloat16* hLo = g_hLo[t & 1];
            rec_stage(Hs, hHi, hLo, tid, 0, 0);
            rec_stage(Hs, hHi, hLo, tid, 1, 1);

            for (int ch = 0; ch < 8; ch++) {
                if (ch == 7) cp_wait0(); else cp_wait1();
                __syncthreads();
                if (ch + 2 < 8) rec_stage(Hs, hHi, hLo, tid, (ch + 2) % 3, ch + 2);

                const unsigned sHbHi = sHs + (unsigned)((ch % 3) * 32768);
                const unsigned sHbLo = sHbHi + 16384u;
                const int kk0 = ch * 4;
#pragma unroll
                for (int kk = 0; kk < 4; kk++) {
                    unsigned ahi[4], alo[4];
                    unsigned boff = abase + (((unsigned)(kk * 32) + ahalf) ^ axor);
                    ldmat4(ahi, sHbHi + boff);
                    ldmat4(alo, sHbLo + boff);
                    const int kkg = kk0 + kk;
                    uint2 bhi0 = Rf2[kkg * 64 + lane];
                    uint2 blo0 = Rf2[2048 + kkg * 64 + lane];
                    uint2 bhi1 = Rf2[kkg * 64 + 32 + lane];
                    uint2 blo1 = Rf2[2048 + kkg * 64 + 32 + lane];
                    mma_bf16(acc0, ahi, bhi0);
                    mma_bf16(acc1, ahi, bhi1);
                    mma_bf16(acc0, ahi, blo0);
                    mma_bf16(acc1, ahi, blo1);
                    mma_bf16(acc0, alo, bhi0);
                    mma_bf16(acc1, alo, bhi1);
                }
            }
            const int g2 = lane >> 2, c2 = lane & 3;
            const int r0 = w * 16 + g2;
            {
                int cb = c2 * 2;
                ps[(cb + 0) * 132 + r0]     = acc0[0];
                ps[(cb + 1) * 132 + r0]     = acc0[1];
                ps[(cb + 0) * 132 + r0 + 8] = acc0[2];
                ps[(cb + 1) * 132 + r0 + 8] = acc0[3];
                cb = 8 + c2 * 2;
                ps[(cb + 0) * 132 + r0]     = acc1[0];
                ps[(cb + 1) * 132 + r0]     = acc1[1];
                ps[(cb + 0) * 132 + r0 + 8] = acc1[2];
                ps[(cb + 1) * 132 + r0 + 8] = acc1[3];
            }
        }
        __syncthreads();

        // gates + state update: thread b handles this block's 4 hidden cols
        if (tid < 128) {
            const int b = tid;
            float z[4][4];
#pragma unroll
            for (int g = 0; g < 4; g++) {
                z[g][0] = xzv[g].x; z[g][1] = xzv[g].y;
                z[g][2] = xzv[g].z; z[g][3] = xzv[g].w;
            }
            if (t > 0) {
#pragma unroll
                for (int g = 0; g < 4; g++)
#pragma unroll
                    for (int j = 0; j < 4; j++)
                        z[g][j] += ps[(g * 4 + j) * 132 + b];
            }
            float hv[4], cvv[4];
#pragma unroll
            for (int j = 0; j < 4; j++) {
                float iv = 1.f / (1.f + __expf(-z[0][j]));
                float fv = 1.f / (1.f + __expf(-z[1][j]));
                float gv = tanhf(z[2][j]);
                float ov = 1.f / (1.f + __expf(-z[3][j]));
                float cc2 = fv * cs[j * 128 + b] + iv * gv;
                cs[j * 128 + b] = cc2;
                cvv[j] = cc2;
                hv[j] = ov * tanhf(cc2);
            }
            float4 h4 = make_float4(hv[0], hv[1], hv[2], hv[3]);
            *(float4*)(out + ((size_t)b * NT + t) * NH + blk * 4) = h4;

            __nv_bfloat16 hiv[4], lov[4];
#pragma unroll
            for (int j = 0; j < 4; j++) { hiv[j] = bhi(hv[j]); lov[j] = blo(hv[j]); }
            const int par = (t + 1) & 1;
            *(uint2*)(g_hHi[par] + (size_t)b * NH + blk * 4) = *(uint2*)hiv;
            *(uint2*)(g_hLo[par] + (size_t)b * NH + blk * 4) = *(uint2*)lov;

            if (t == NT - 1) {
                size_t off1 = (size_t)NB * NT * NH;
                *(float4*)(out + off1 + (size_t)b * NH + blk * 4) = h4;
                float4 c4 = make_float4(cvv[0], cvv[1], cvv[2], cvv[3]);
                *(float4*)(out + off1 + (size_t)NB * NH + (size_t)b * NH + blk * 4) = c4;
            }
        }

        // grid barrier (monotonic counter; reset by conv_kernel each launch)
        if (t < NT - 1) {
            __threadfence();
            __syncthreads();
            if (tid == 0) {
                atomicAdd(&g_bar, 1u);
                const unsigned target = (unsigned)NBLK * (unsigned)(t + 1);
                while (*((volatile unsigned*)&g_bar) < target) {}
                __threadfence();
            }
            __syncthreads();
        }
    }
}

// ---------------------------------------------------------------------------
extern "C" void kernel_launch(void* const* d_in, const int* in_sizes, int n_in,
                              void* d_out, int out_size) {
    const float* x    = (const float*)d_in[0];  // [B,T,F]
    const float* w    = (const float*)d_in[1];  // [F,4H]
    const float* rk   = (const float*)d_in[2];  // [H,4H]
    const float* bias = (const float*)d_in[3];  // [4H]
    float* out = (float*)d_out;                 // output | h | c

    cudaFuncSetAttribute(xza_kernel,
                         cudaFuncAttributeMaxDynamicSharedMemorySize, 131072);
    cudaFuncSetAttribute(lstm_rec_kernel,
                         cudaFuncAttributeMaxDynamicSharedMemorySize, 141568);

    conv_kernel<<<2048, 256>>>(x, w);
    xza_kernel<<<dim3(16, 512), 256, 131072>>>(bias);
    lstm_rec_kernel<<<NBLK, 256, 141568>>>(rk, out);
}